// round 14
// baseline (speedup 1.0000x reference)
#include <cuda_runtime.h>
#include <cuda_fp16.h>

#define NUM_U 50000
#define NUM_I 50000
#define NE    1000000

// ---------------- device scratch (static, allocation-free) ----------------
__device__ float   g_Ct[64 * 32];       // Ct[k][j] = C[j][k] (composed weights)
__device__ float   g_cab[128];          // ca[64] | cb[64]
__device__ float   g_m1u[NUM_U * 32];   // t32 = q @ C.T (fp32 self term)
__device__ float   g_m1i[NUM_I * 32];
__device__ __half2 g_h1u[NUM_U * 16];   // fp16 mirror of t32 (gather, 64B rows)
__device__ __half2 g_h1i[NUM_I * 16];
__device__ float4  g_t3u[NUM_U];        // (pa1, ta, tb, 0) per node
__device__ float4  g_t3i[NUM_I];
__device__ float   g_pb1_u[NUM_U], g_pb1_i[NUM_I];
__device__ float   g_m2u[NUM_U * 32];   // [z2|v2] self (fp32)
__device__ float   g_m2i[NUM_I * 32];
__device__ __half2 g_h2u[NUM_U * 16];   // fp16 mirror of m2 (gather, 64B rows)
__device__ __half2 g_h2i[NUM_I * 16];
__device__ float   g_pa2_u[NUM_U], g_pb2_u[NUM_U];
__device__ float   g_pa2_i[NUM_I], g_pb2_i[NUM_I];
__device__ float   g_hv[(NUM_U + NUM_I) * 32];   // per-output-row hv (users, items)
__device__ int     g_cnt_i[NUM_I], g_cnt_u[NUM_U];   // zero-init; re-zeroed by k_scan
__device__ int     g_cur_i[NUM_I], g_cur_u[NUM_U];
__device__ int     g_rp_i[NUM_I + 1], g_rp_u[NUM_U + 1];
__device__ int     g_col_i[NE];
__device__ int     g_col_u[NE];

// ---------------- launch 0: histogram + one-time weight composition -------------
__global__ void __launch_bounds__(256) k_hist_compose(
    const int* __restrict__ src, const int* __restrict__ dst,
    const float* __restrict__ W1, const float* __restrict__ Wupd2,
    const float* __restrict__ WV2, const float* __restrict__ watt2) {
    int tid = threadIdx.x;
    if (blockIdx.x == 0) {
        for (int idx = tid; idx < 2048; idx += 256) {
            int j = idx >> 6, k = idx & 63;
            const float* R = (j < 16) ? (Wupd2 + j * 64) : (WV2 + (j - 16) * 64);
            float acc = 0.f;
            #pragma unroll 8
            for (int m = 0; m < 64; m++) acc = fmaf(R[m], W1[m * 64 + k], acc);
            g_Ct[k * 32 + j] = acc;
        }
        if (tid < 128) {
            int which = tid >> 6, k = tid & 63;
            const float* R = watt2 + which * 64;
            float acc = 0.f;
            #pragma unroll 8
            for (int m = 0; m < 64; m++) acc = fmaf(R[m], W1[m * 64 + k], acc);
            g_cab[which * 64 + k] = acc;
        }
    }
    int nthread = gridDim.x * 256;
    for (int e = blockIdx.x * 256 + tid; e < NE; e += nthread) {
        atomicAdd(&g_cnt_i[dst[e]], 1);
        atomicAdd(&g_cnt_u[src[e]], 1);
    }
}

// ---------------- launch 1: scan (re-zeros cnt for next replay) ----------------
__global__ void k_scan() {
    const int n = blockIdx.x ? NUM_U : NUM_I;
    int* cnt    = blockIdx.x ? g_cnt_u : g_cnt_i;
    int* cur    = blockIdx.x ? g_cur_u : g_cur_i;
    int* rp     = blockIdx.x ? g_rp_u  : g_rp_i;
    __shared__ int ssum[1024];
    int t = threadIdx.x;
    int C = (n + 1023) / 1024;
    int b = t * C;
    int e = min(n, b + C);
    int s = 0;
    #pragma unroll 4
    for (int i = b; i < e; i++) s += cnt[i];
    ssum[t] = s;
    __syncthreads();
    for (int off = 1; off < 1024; off <<= 1) {
        int v = (t >= off) ? ssum[t - off] : 0;
        __syncthreads();
        ssum[t] += v;
        __syncthreads();
    }
    int run = ssum[t] - s;
    for (int i = b; i < e; i++) {
        int c = cnt[i];
        rp[i]  = run;
        cur[i] = run;
        cnt[i] = 0;
        run += c;
    }
    if (t == 1023) rp[n] = ssum[1023];
}

// ---------------- launch 2: interleaved scatter + node precompute ---------------
__global__ void __launch_bounds__(256, 6) k_scatter_prep(
    const int* __restrict__ src, const int* __restrict__ dst,
    const float* __restrict__ Qu, const float* __restrict__ Qi,
    const float* __restrict__ watt1) {
    __shared__ float sCt[64 * 36];   // sCt[k*36 + j] = C[j][k]
    __shared__ float sca[64], scb[64];
    __shared__ float sx[8][64];
    int tid = threadIdx.x;
    for (int idx = tid; idx < 2048; idx += 256) {
        int j = idx & 31, k = idx >> 5;
        sCt[k * 36 + j] = g_Ct[idx];
    }
    if (tid < 64)  sca[tid] = g_cab[tid];
    else if (tid < 128) scb[tid - 64] = g_cab[tid];
    __syncthreads();

    int w = tid >> 5, lane = tid & 31;
    int gwarp = blockIdx.x * 8 + w;
    const int NW = gridDim.x * 8;
    const int NCHUNK = NE / 32;              // 31250 exact

    float2 w1a = reinterpret_cast<const float2*>(watt1)[lane];
    float2 w1b = reinterpret_cast<const float2*>(watt1)[32 + lane];
    float2 cav = make_float2(sca[2 * lane], sca[2 * lane + 1]);
    float2 cbv = make_float2(scb[2 * lane], scb[2 * lane + 1]);

    const int ITERS = (NCHUNK + NW - 1) / NW;
    const int NITER = (NUM_U + NUM_I + 3 * NW - 1) / (3 * NW);
    const int TOT   = (ITERS > NITER) ? ITERS : NITER;

    for (int it = 0; it < TOT; ++it) {
        int c = gwarp + it * NW;
        int s = 0, d = 0, p = 0, q = 0;
        bool has_e = (c < NCHUNK);
        if (has_e) {
            int e = c * 32 + lane;
            s = src[e];
            d = dst[e];
            p = atomicAdd(&g_cur_i[d], 1);
            q = atomicAdd(&g_cur_u[s], 1);
        }

        #pragma unroll
        for (int r = 0; r < 3; ++r) {
            int gw = gwarp + (it * 3 + r) * NW;
            if (gw < NUM_U + NUM_I) {
                const float* qv_p; float* m1; __half2* h1; float4* t3; float* pb1; int nd;
                if (gw < NUM_U) { nd = gw;         qv_p = Qu; m1 = g_m1u; h1 = g_h1u; t3 = g_t3u; pb1 = g_pb1_u; }
                else            { nd = gw - NUM_U; qv_p = Qi; m1 = g_m1i; h1 = g_h1i; t3 = g_t3i; pb1 = g_pb1_i; }

                float2 qv = reinterpret_cast<const float2*>(qv_p)[nd * 32 + lane];
                sx[w][2 * lane]     = qv.x;
                sx[w][2 * lane + 1] = qv.y;
                float da = qv.x * w1a.x + qv.y * w1a.y;
                float db = qv.x * w1b.x + qv.y * w1b.y;
                float ta = qv.x * cav.x + qv.y * cav.y;
                float tb = qv.x * cbv.x + qv.y * cbv.y;
                #pragma unroll
                for (int o = 16; o; o >>= 1) {
                    da += __shfl_xor_sync(0xffffffffu, da, o);
                    db += __shfl_xor_sync(0xffffffffu, db, o);
                    ta += __shfl_xor_sync(0xffffffffu, ta, o);
                    tb += __shfl_xor_sync(0xffffffffu, tb, o);
                }
                if (lane == 0) {
                    t3[nd]  = make_float4(da, ta, tb, 0.f);
                    pb1[nd] = db;
                }
                __syncwarp();

                float acc = 0.f;
                #pragma unroll
                for (int k = 0; k < 64; k++) acc = fmaf(sx[w][k], sCt[k * 36 + lane], acc);
                m1[nd * 32 + lane] = acc;
                float other = __shfl_xor_sync(0xffffffffu, acc, 1);
                if (!(lane & 1)) h1[nd * 16 + (lane >> 1)] = __floats2half2_rn(acc, other);
                __syncwarp();
            }
        }

        if (has_e) {
            g_col_i[p] = s;
            g_col_u[q] = d;
        }
    }
}

// 4-neighbor gather: lane groups of 8; each lane 8B of a 64B fp16 row
#define AGG_GATHER4(f4, a0, a1, a2, a3, w_, nbr, cnt, grp, myoff)                      \
    _Pragma("unroll 4")                                                                \
    for (int t = 0; t < cnt; t += 4) {                                                 \
        int srcl = t + (grp);                                                          \
        float wt = __shfl_sync(0xffffffffu, w_, srcl);                                 \
        int   nb = __shfl_sync(0xffffffffu, nbr, srcl);                                \
        uint2 pv = (f4)[nb * 8 + (myoff)];                                             \
        float2 v0 = __half22float2(*reinterpret_cast<__half2*>(&pv.x));                \
        float2 v1 = __half22float2(*reinterpret_cast<__half2*>(&pv.y));                \
        a0 = fmaf(wt, v0.x, a0);                                                       \
        a1 = fmaf(wt, v0.y, a1);                                                       \
        a2 = fmaf(wt, v1.x, a2);                                                       \
        a3 = fmaf(wt, v1.y, a3);                                                       \
    }

#define AGG_REDUCE4(a0, a1, a2, a3)                                                    \
    a0 += __shfl_xor_sync(0xffffffffu, a0, 8);                                         \
    a1 += __shfl_xor_sync(0xffffffffu, a1, 8);                                         \
    a2 += __shfl_xor_sync(0xffffffffu, a2, 8);                                         \
    a3 += __shfl_xor_sync(0xffffffffu, a3, 8);                                         \
    a0 += __shfl_xor_sync(0xffffffffu, a0, 16);                                        \
    a1 += __shfl_xor_sync(0xffffffffu, a1, 16);                                        \
    a2 += __shfl_xor_sync(0xffffffffu, a2, 16);                                        \
    a3 += __shfl_xor_sync(0xffffffffu, a3, 16);

// ---------------- launch 3: layer-1 agg on t32 + layer-2 self terms -------------
__global__ void __launch_bounds__(256, 6) k_agg1() {
    int tid  = threadIdx.x;
    int lane = tid & 31;
    int grp   = lane >> 3;
    int myoff = lane & 7;
    int nwarp = (gridDim.x * blockDim.x) >> 5;

    for (int gw = (blockIdx.x * 256 + tid) >> 5; gw < NUM_U + NUM_I; gw += nwarp) {
        const uint2* f4; const float4* t3n; const int* rp; const int* col;
        const float* m1s; const float4* t3s;
        float* m2; __half2* h2; float* pa2; float* pb2; float pbn; int nd;
        if (gw < NUM_I) {
            nd = gw;         f4 = reinterpret_cast<const uint2*>(g_h1u);
            t3n = g_t3u; pbn = g_pb1_i[nd]; rp = g_rp_i; col = g_col_i;
            m1s = g_m1i; t3s = g_t3i;
            m2 = g_m2i; h2 = g_h2i; pa2 = g_pa2_i; pb2 = g_pb2_i;
        } else {
            nd = gw - NUM_I; f4 = reinterpret_cast<const uint2*>(g_h1i);
            t3n = g_t3i; pbn = g_pb1_u[nd]; rp = g_rp_u; col = g_col_u;
            m1s = g_m1u; t3s = g_t3u;
            m2 = g_m2u; h2 = g_h2u; pa2 = g_pa2_u; pb2 = g_pb2_u;
        }
        int beg = rp[nd];
        int end = rp[nd + 1];
        float a0 = 0.f, a1 = 0.f, a2 = 0.f, a3 = 0.f;
        float ssum = 0.f, sa = 0.f, sb = 0.f;

        for (int base = beg; base < end; base += 32) {
            int j = base + lane;
            float w_ = 0.f, ta_n = 0.f, tb_n = 0.f;
            int nbr = 0;
            if (j < end) {
                nbr = col[j];
                float4 t = t3n[nbr];
                float x  = t.x + pbn;
                float sg = __fdividef(1.f, 1.f + __expf(-x));
                w_ = __expf(sg);
                ta_n = t.y; tb_n = t.z;
            }
            ssum += w_;
            sa = fmaf(w_, ta_n, sa);
            sb = fmaf(w_, tb_n, sb);
            int cnt = min(32, end - base);
            AGG_GATHER4(f4, a0, a1, a2, a3, w_, nbr, cnt, grp, myoff);
        }
        AGG_REDUCE4(a0, a1, a2, a3);
        #pragma unroll
        for (int o = 16; o; o >>= 1) {
            ssum += __shfl_xor_sync(0xffffffffu, ssum, o);
            sa   += __shfl_xor_sync(0xffffffffu, sa, o);
            sb   += __shfl_xor_sync(0xffffffffu, sb, o);
        }
        float inv = (end > beg) ? __fdividef(1.f, fmaxf(ssum, 1e-12f)) : 0.f;

        if (lane == 0) {
            float4 ts = t3s[nd];
            pa2[nd] = fmaf(sa, inv, ts.y);
            pb2[nd] = fmaf(sb, inv, ts.z);
        }
        if (lane < 8) {
            float4 ms = reinterpret_cast<const float4*>(m1s)[nd * 8 + myoff];
            float4 o = make_float4(fmaf(a0, inv, ms.x), fmaf(a1, inv, ms.y),
                                   fmaf(a2, inv, ms.z), fmaf(a3, inv, ms.w));
            reinterpret_cast<float4*>(m2)[nd * 8 + myoff] = o;
            h2[nd * 16 + 2 * myoff]     = __floats2half2_rn(o.x, o.y);
            h2[nd * 16 + 2 * myoff + 1] = __floats2half2_rn(o.z, o.w);
        }
        __syncwarp();
    }
}

// ---------------- launch 4: layer-2 agg (on m2) -> hv rows ----------------------
__global__ void __launch_bounds__(256, 6) k_agg2(const float* __restrict__ bV2) {
    __shared__ float sb2[16];
    int tid = threadIdx.x;
    if (tid < 16) sb2[tid] = bV2[tid];
    __syncthreads();

    int lane = tid & 31;
    int grp   = lane >> 3;
    int myoff = lane & 7;
    int nwarp = (gridDim.x * blockDim.x) >> 5;

    for (int gw = (blockIdx.x * 256 + tid) >> 5; gw < NUM_U + NUM_I; gw += nwarp) {
        const uint2* f4; const float* pa; const int* rp; const int* col;
        const float* m2; float pbn; int nd; int row;
        if (gw < NUM_I) {
            nd = gw;         f4 = reinterpret_cast<const uint2*>(g_h2u);
            pa = g_pa2_u; pbn = g_pb2_i[nd]; rp = g_rp_i; col = g_col_i;
            m2 = g_m2i; row = NUM_U + nd;
        } else {
            nd = gw - NUM_I; f4 = reinterpret_cast<const uint2*>(g_h2i);
            pa = g_pa2_i; pbn = g_pb2_u[nd]; rp = g_rp_u; col = g_col_u;
            m2 = g_m2u; row = nd;
        }
        int beg = rp[nd];
        int end = rp[nd + 1];
        float a0 = 0.f, a1 = 0.f, a2 = 0.f, a3 = 0.f, ssum = 0.f;

        for (int base = beg; base < end; base += 32) {
            int j = base + lane;
            float w_ = 0.f;
            int nbr = 0;
            if (j < end) {
                nbr = col[j];
                float x  = pa[nbr] + pbn;
                float sg = __fdividef(1.f, 1.f + __expf(-x));
                w_ = __expf(sg);
            }
            ssum += w_;
            int cnt = min(32, end - base);
            AGG_GATHER4(f4, a0, a1, a2, a3, w_, nbr, cnt, grp, myoff);
        }
        AGG_REDUCE4(a0, a1, a2, a3);
        #pragma unroll
        for (int o = 16; o; o >>= 1) ssum += __shfl_xor_sync(0xffffffffu, ssum, o);
        float inv = (end > beg) ? __fdividef(1.f, fmaxf(ssum, 1e-12f)) : 0.f;
        float sflag = (end > beg) ? 1.f : 0.f;

        if (lane < 8) {
            float4 o = make_float4(a0 * inv, a1 * inv, a2 * inv, a3 * inv);
            if (myoff < 4) {
                float4 zs = reinterpret_cast<const float4*>(m2)[nd * 8 + myoff];
                o.x += zs.x; o.y += zs.y; o.z += zs.z; o.w += zs.w;
            } else {
                int jb = 4 * (myoff - 4);
                o.x += sb2[jb] * sflag;     o.y += sb2[jb + 1] * sflag;
                o.z += sb2[jb + 2] * sflag; o.w += sb2[jb + 3] * sflag;
            }
            reinterpret_cast<float4*>(g_hv)[row * 8 + myoff] = o;
        }
        __syncwarp();
    }
}

// ---------------- launch 5: streaming epilogue: fc + relu + E concat ------------
__global__ void __launch_bounds__(256, 6) k_epi(
    const float* __restrict__ Eu, const float* __restrict__ Ei,
    const float* __restrict__ Wfc, const float* __restrict__ bfc,
    float* __restrict__ outp) {
    __shared__ float2 sWf[32 * 33];  // sWf[k*33+l] = (Wfc[l][k], Wfc[l+32][k])
    __shared__ float  sbf[64];
    int tid = threadIdx.x;
    for (int idx = tid; idx < 2048; idx += 256) {
        int j = idx >> 5, k = idx & 31;
        reinterpret_cast<float*>(sWf)[(k * 33 + (j & 31)) * 2 + (j >> 5)] = Wfc[idx];
    }
    if (tid < 64) sbf[tid] = bfc[tid];
    __syncthreads();

    int lane = tid & 31;
    int nwarp = (gridDim.x * blockDim.x) >> 5;

    for (int row = (blockIdx.x * 256 + tid) >> 5; row < NUM_U + NUM_I; row += nwarp) {
        const float* Eemb = (row < NUM_U) ? (Eu + (size_t)row * 64)
                                          : (Ei + (size_t)(row - NUM_U) * 64);
        float hvv = g_hv[row * 32 + lane];   // lane k holds hv[k]

        float g0 = sbf[lane], g1 = sbf[lane + 32];
        #pragma unroll
        for (int k = 0; k < 32; k++) {
            float  c  = __shfl_sync(0xffffffffu, hvv, k);
            float2 wv = sWf[k * 33 + lane];
            g0 = fmaf(c, wv.x, g0);
            g1 = fmaf(c, wv.y, g1);
        }
        g0 = fmaxf(g0, 0.f);
        g1 = fmaxf(g1, 0.f);

        float2 ev = reinterpret_cast<const float2*>(Eemb)[lane];
        float* orow = outp + (size_t)row * 128;
        reinterpret_cast<float2*>(orow)[lane] = ev;
        orow[64 + lane] = g0;
        orow[96 + lane] = g1;
    }
}

// ---------------- host launcher ----------------
extern "C" void kernel_launch(void* const* d_in, const int* in_sizes, int n_in,
                              void* d_out, int out_size) {
    const float* E_u   = (const float*)d_in[0];
    const float* E_i   = (const float*)d_in[1];
    const float* Q_u   = (const float*)d_in[2];
    const float* Q_i   = (const float*)d_in[3];
    const float* Watt1 = (const float*)d_in[4];
    const float* Wupd1 = (const float*)d_in[5];
    const float* Watt2 = (const float*)d_in[8];
    const float* Wupd2 = (const float*)d_in[9];
    const float* WV2   = (const float*)d_in[10];
    const float* bV2   = (const float*)d_in[11];
    const float* Wfc   = (const float*)d_in[12];
    const float* bfc   = (const float*)d_in[13];
    const int*   src   = (const int*)d_in[14];
    const int*   dst   = (const int*)d_in[15];
    float* out = (float*)d_out;

    const int GB = 148 * 6;   // one residency wave at 6 blocks/SM

    k_hist_compose<<<1184, 256>>>(src, dst, Wupd1, Wupd2, WV2, Watt2); // 0
    k_scan<<<2, 1024>>>();                                             // 1
    k_scatter_prep<<<GB, 256>>>(src, dst, Q_u, Q_i, Watt1);            // 2
    k_agg1<<<GB, 256>>>();                                             // 3 ← profiled
    k_agg2<<<GB, 256>>>(bV2);                                          // 4
    k_epi<<<GB, 256>>>(E_u, E_i, Wfc, bfc, out);                       // 5
}

// round 15
// speedup vs baseline: 1.0503x; 1.0503x over previous
#include <cuda_runtime.h>
#include <cuda_fp16.h>

#define NUM_U 50000
#define NUM_I 50000
#define NE    1000000

// ---------------- device scratch (static, allocation-free) ----------------
__device__ float   g_Ct[64 * 32];       // Ct[k][j] = C[j][k] (composed weights)
__device__ float   g_m1u[NUM_U * 32];   // t32 = q @ C.T (fp32 self term)
__device__ float   g_m1i[NUM_I * 32];
__device__ __half2 g_h1u[NUM_U * 16];   // fp16 mirror of t32 (gather, 64B rows)
__device__ __half2 g_h1i[NUM_I * 16];
__device__ float4  g_t3u[NUM_U];        // (pa1, ta, tb, pb1) per node
__device__ float4  g_t3i[NUM_I];
__device__ float   g_m2u[NUM_U * 32];   // [z2|v2] self (fp32)
__device__ float   g_m2i[NUM_I * 32];
__device__ __half2 g_h2u[NUM_U * 16];   // fp16 mirror of m2 (gather, 64B rows)
__device__ __half2 g_h2i[NUM_I * 16];
__device__ float   g_pa2_u[NUM_U], g_pb2_u[NUM_U];
__device__ float   g_pa2_i[NUM_I], g_pb2_i[NUM_I];
__device__ float2  g_w_i[NE];           // per-edge (w, half2(w*ta, w*tb)), item-side CSR order
__device__ float2  g_w_u[NE];           // user-side CSR order
__device__ float   g_hvpad[1];          // (unused)
__device__ int     g_cnt_i[NUM_I], g_cnt_u[NUM_U];   // zero-init; re-zeroed by k_scan
__device__ int     g_cur_i[NUM_I], g_cur_u[NUM_U];
__device__ int     g_rp_i[NUM_I + 1], g_rp_u[NUM_U + 1];
__device__ int     g_col_i[NE];
__device__ int     g_col_u[NE];

__device__ __forceinline__ float edge_w(float x) {
    float sg = __fdividef(1.f, 1.f + __expf(-x));
    return __expf(sg);
}

// ---- launch 0: histogram + weight composition + light node projections --------
// every block composes ca/cb locally (cheap); block 0 also writes g_Ct.
// per node: t3 = (pa1, ta, tb, pb1)
__global__ void __launch_bounds__(256) k_hist_prep0(
    const int* __restrict__ src, const int* __restrict__ dst,
    const float* __restrict__ Qu, const float* __restrict__ Qi,
    const float* __restrict__ watt1, const float* __restrict__ W1,
    const float* __restrict__ Wupd2, const float* __restrict__ WV2,
    const float* __restrict__ watt2) {
    __shared__ float sca[64], scb[64];
    int tid = threadIdx.x;
    if (tid < 128) {
        int which = tid >> 6, k = tid & 63;
        const float* R = watt2 + which * 64;
        float acc = 0.f;
        #pragma unroll 8
        for (int m = 0; m < 64; m++) acc = fmaf(R[m], W1[m * 64 + k], acc);
        (which ? scb : sca)[k] = acc;
    }
    if (blockIdx.x == 0) {
        for (int idx = tid; idx < 2048; idx += 256) {
            int j = idx >> 6, k = idx & 63;
            const float* R = (j < 16) ? (Wupd2 + j * 64) : (WV2 + (j - 16) * 64);
            float acc = 0.f;
            #pragma unroll 8
            for (int m = 0; m < 64; m++) acc = fmaf(R[m], W1[m * 64 + k], acc);
            g_Ct[k * 32 + j] = acc;
        }
    }
    __syncthreads();

    int nthread = gridDim.x * 256;
    for (int e = blockIdx.x * 256 + tid; e < NE; e += nthread) {
        atomicAdd(&g_cnt_i[dst[e]], 1);
        atomicAdd(&g_cnt_u[src[e]], 1);
    }

    int lane = tid & 31;
    int nwarp = nthread >> 5;
    float2 w1a = reinterpret_cast<const float2*>(watt1)[lane];
    float2 w1b = reinterpret_cast<const float2*>(watt1)[32 + lane];
    float2 cav = make_float2(sca[2 * lane], sca[2 * lane + 1]);
    float2 cbv = make_float2(scb[2 * lane], scb[2 * lane + 1]);

    for (int gw = (blockIdx.x * 256 + tid) >> 5; gw < NUM_U + NUM_I; gw += nwarp) {
        const float* q; float4* t3; int nd;
        if (gw < NUM_U) { nd = gw;         q = Qu; t3 = g_t3u; }
        else            { nd = gw - NUM_U; q = Qi; t3 = g_t3i; }
        float2 qv = reinterpret_cast<const float2*>(q)[nd * 32 + lane];
        float da = qv.x * w1a.x + qv.y * w1a.y;
        float db = qv.x * w1b.x + qv.y * w1b.y;
        float ta = qv.x * cav.x + qv.y * cav.y;
        float tb = qv.x * cbv.x + qv.y * cbv.y;
        #pragma unroll
        for (int o = 16; o; o >>= 1) {
            da += __shfl_xor_sync(0xffffffffu, da, o);
            db += __shfl_xor_sync(0xffffffffu, db, o);
            ta += __shfl_xor_sync(0xffffffffu, ta, o);
            tb += __shfl_xor_sync(0xffffffffu, tb, o);
        }
        if (lane == 0) t3[nd] = make_float4(da, ta, tb, db);
    }
}

// ---------------- launch 1: scan (re-zeros cnt for next replay) ----------------
__global__ void k_scan() {
    const int n = blockIdx.x ? NUM_U : NUM_I;
    int* cnt    = blockIdx.x ? g_cnt_u : g_cnt_i;
    int* cur    = blockIdx.x ? g_cur_u : g_cur_i;
    int* rp     = blockIdx.x ? g_rp_u  : g_rp_i;
    __shared__ int ssum[1024];
    int t = threadIdx.x;
    int C = (n + 1023) / 1024;
    int b = t * C;
    int e = min(n, b + C);
    int s = 0;
    #pragma unroll 4
    for (int i = b; i < e; i++) s += cnt[i];
    ssum[t] = s;
    __syncthreads();
    for (int off = 1; off < 1024; off <<= 1) {
        int v = (t >= off) ? ssum[t - off] : 0;
        __syncthreads();
        ssum[t] += v;
        __syncthreads();
    }
    int run = ssum[t] - s;
    for (int i = b; i < e; i++) {
        int c = cnt[i];
        rp[i]  = run;
        cur[i] = run;
        cnt[i] = 0;
        run += c;
    }
    if (t == 1023) rp[n] = ssum[1023];
}

// ---- launch 2: interleaved scatter (+ per-edge weight precompute) + m1 GEMV ----
__global__ void __launch_bounds__(256, 6) k_scatter_prep(
    const int* __restrict__ src, const int* __restrict__ dst,
    const float* __restrict__ Qu, const float* __restrict__ Qi) {
    __shared__ float sCt[64 * 36];   // sCt[k*36 + j] = C[j][k]
    __shared__ float sx[8][64];
    int tid = threadIdx.x;
    for (int idx = tid; idx < 2048; idx += 256) {
        int j = idx & 31, k = idx >> 5;
        sCt[k * 36 + j] = g_Ct[idx];
    }
    __syncthreads();

    int w = tid >> 5, lane = tid & 31;
    int gwarp = blockIdx.x * 8 + w;
    const int NW = gridDim.x * 8;
    const int NCHUNK = NE / 32;              // 31250 exact

    const int ITERS = (NCHUNK + NW - 1) / NW;
    const int NITER = (NUM_U + NUM_I + 3 * NW - 1) / (3 * NW);
    const int TOT   = (ITERS > NITER) ? ITERS : NITER;

    for (int it = 0; it < TOT; ++it) {
        // ---- phase A: edge loads + atomics + edge-weight computation ----
        int c = gwarp + it * NW;
        int s = 0, d = 0, p = 0, q = 0;
        float2 pwi = make_float2(0.f, 0.f), pwu = make_float2(0.f, 0.f);
        bool has_e = (c < NCHUNK);
        if (has_e) {
            int e = c * 32 + lane;
            s = src[e];
            d = dst[e];
            float4 tu = g_t3u[s];
            float4 ti = g_t3i[d];
            p = atomicAdd(&g_cur_i[d], 1);
            q = atomicAdd(&g_cur_u[s], 1);
            float wi = edge_w(tu.x + ti.w);   // pa1_u[s] + pb1_i[d]
            float wu = edge_w(ti.x + tu.w);   // pa1_i[d] + pb1_u[s]
            __half2 hi = __floats2half2_rn(wi * tu.y, wi * tu.z);
            __half2 hu = __floats2half2_rn(wu * ti.y, wu * ti.z);
            pwi.x = wi; pwi.y = *reinterpret_cast<float*>(&hi);
            pwu.x = wu; pwu.y = *reinterpret_cast<float*>(&hu);
        }

        // ---- phase B: 3 nodes of m1 GEMV + h1 mirror (hides phase-A latency) ----
        #pragma unroll
        for (int r = 0; r < 3; ++r) {
            int gw = gwarp + (it * 3 + r) * NW;
            if (gw < NUM_U + NUM_I) {
                const float* qv_p; float* m1; __half2* h1; int nd;
                if (gw < NUM_U) { nd = gw;         qv_p = Qu; m1 = g_m1u; h1 = g_h1u; }
                else            { nd = gw - NUM_U; qv_p = Qi; m1 = g_m1i; h1 = g_h1i; }

                float2 qv = reinterpret_cast<const float2*>(qv_p)[nd * 32 + lane];
                sx[w][2 * lane]     = qv.x;
                sx[w][2 * lane + 1] = qv.y;
                __syncwarp();
                float acc = 0.f;
                #pragma unroll
                for (int k = 0; k < 64; k++) acc = fmaf(sx[w][k], sCt[k * 36 + lane], acc);
                m1[nd * 32 + lane] = acc;
                float other = __shfl_xor_sync(0xffffffffu, acc, 1);
                if (!(lane & 1)) h1[nd * 16 + (lane >> 1)] = __floats2half2_rn(acc, other);
                __syncwarp();
            }
        }

        // ---- phase C: consume atomic results ----
        if (has_e) {
            g_col_i[p] = s;
            g_w_i[p]   = pwi;
            g_col_u[q] = d;
            g_w_u[q]   = pwu;
        }
    }
}

// 4-neighbor gather: lane groups of 8; each lane 8B of a 64B fp16 row
#define AGG_GATHER4(f4, a0, a1, a2, a3, w_, nbr, cnt, grp, myoff)                      \
    _Pragma("unroll 4")                                                                \
    for (int t = 0; t < cnt; t += 4) {                                                 \
        int srcl = t + (grp);                                                          \
        float wt = __shfl_sync(0xffffffffu, w_, srcl);                                 \
        int   nb = __shfl_sync(0xffffffffu, nbr, srcl);                                \
        uint2 pv = (f4)[nb * 8 + (myoff)];                                             \
        float2 v0 = __half22float2(*reinterpret_cast<__half2*>(&pv.x));                \
        float2 v1 = __half22float2(*reinterpret_cast<__half2*>(&pv.y));                \
        a0 = fmaf(wt, v0.x, a0);                                                       \
        a1 = fmaf(wt, v0.y, a1);                                                       \
        a2 = fmaf(wt, v1.x, a2);                                                       \
        a3 = fmaf(wt, v1.y, a3);                                                       \
    }

#define AGG_REDUCE4(a0, a1, a2, a3)                                                    \
    a0 += __shfl_xor_sync(0xffffffffu, a0, 8);                                         \
    a1 += __shfl_xor_sync(0xffffffffu, a1, 8);                                         \
    a2 += __shfl_xor_sync(0xffffffffu, a2, 8);                                         \
    a3 += __shfl_xor_sync(0xffffffffu, a3, 8);                                         \
    a0 += __shfl_xor_sync(0xffffffffu, a0, 16);                                        \
    a1 += __shfl_xor_sync(0xffffffffu, a1, 16);                                        \
    a2 += __shfl_xor_sync(0xffffffffu, a2, 16);                                        \
    a3 += __shfl_xor_sync(0xffffffffu, a3, 16);

// ---- launch 3: layer-1 agg (precomputed edge weights) + layer-2 self terms -----
__global__ void __launch_bounds__(256, 6) k_agg1() {
    int tid  = threadIdx.x;
    int lane = tid & 31;
    int grp   = lane >> 3;
    int myoff = lane & 7;
    int nwarp = (gridDim.x * blockDim.x) >> 5;

    for (int gw = (blockIdx.x * 256 + tid) >> 5; gw < NUM_U + NUM_I; gw += nwarp) {
        const uint2* f4; const int* rp; const int* col; const float2* wv;
        const float* m1s; const float4* t3s;
        float* m2; __half2* h2; float* pa2; float* pb2; int nd;
        if (gw < NUM_I) {
            nd = gw;         f4 = reinterpret_cast<const uint2*>(g_h1u);
            rp = g_rp_i; col = g_col_i; wv = g_w_i;
            m1s = g_m1i; t3s = g_t3i;
            m2 = g_m2i; h2 = g_h2i; pa2 = g_pa2_i; pb2 = g_pb2_i;
        } else {
            nd = gw - NUM_I; f4 = reinterpret_cast<const uint2*>(g_h1i);
            rp = g_rp_u; col = g_col_u; wv = g_w_u;
            m1s = g_m1u; t3s = g_t3u;
            m2 = g_m2u; h2 = g_h2u; pa2 = g_pa2_u; pb2 = g_pb2_u;
        }
        int beg = rp[nd];
        int end = rp[nd + 1];
        float a0 = 0.f, a1 = 0.f, a2 = 0.f, a3 = 0.f;
        float ssum = 0.f, sa = 0.f, sb = 0.f;

        for (int base = beg; base < end; base += 32) {
            int j = base + lane;
            float w_ = 0.f;
            int nbr = 0;
            if (j < end) {
                nbr = col[j];
                float2 pw = wv[j];
                w_ = pw.x;
                float2 t = __half22float2(*reinterpret_cast<__half2*>(&pw.y));
                sa += t.x;
                sb += t.y;
            }
            ssum += w_;
            int cnt = min(32, end - base);
            AGG_GATHER4(f4, a0, a1, a2, a3, w_, nbr, cnt, grp, myoff);
        }
        AGG_REDUCE4(a0, a1, a2, a3);
        #pragma unroll
        for (int o = 16; o; o >>= 1) {
            ssum += __shfl_xor_sync(0xffffffffu, ssum, o);
            sa   += __shfl_xor_sync(0xffffffffu, sa, o);
            sb   += __shfl_xor_sync(0xffffffffu, sb, o);
        }
        float inv = (end > beg) ? __fdividef(1.f, fmaxf(ssum, 1e-12f)) : 0.f;

        if (lane == 0) {
            float4 ts = t3s[nd];
            pa2[nd] = fmaf(sa, inv, ts.y);
            pb2[nd] = fmaf(sb, inv, ts.z);
        }
        if (lane < 8) {
            float4 ms = reinterpret_cast<const float4*>(m1s)[nd * 8 + myoff];
            float4 o = make_float4(fmaf(a0, inv, ms.x), fmaf(a1, inv, ms.y),
                                   fmaf(a2, inv, ms.z), fmaf(a3, inv, ms.w));
            reinterpret_cast<float4*>(m2)[nd * 8 + myoff] = o;
            h2[nd * 16 + 2 * myoff]     = __floats2half2_rn(o.x, o.y);
            h2[nd * 16 + 2 * myoff + 1] = __floats2half2_rn(o.z, o.w);
        }
        __syncwarp();
    }
}

// ---------------- launch 4: layer-2 agg (on m2) + fc + output concat ------------
__global__ void __launch_bounds__(256, 6) k_agg_final(
    const float* __restrict__ Eu, const float* __restrict__ Ei,
    const float* __restrict__ bV2, const float* __restrict__ Wfc,
    const float* __restrict__ bfc, float* __restrict__ outp) {

    __shared__ float2 sWf[32 * 33];  // sWf[k*33+l] = (Wfc[l][k], Wfc[l+32][k])
    __shared__ float  shv[8][32];
    __shared__ float  sb2[16], sbf[64];
    int tid = threadIdx.x;
    for (int idx = tid; idx < 2048; idx += 256) {
        int j = idx >> 5, k = idx & 31;
        reinterpret_cast<float*>(sWf)[(k * 33 + (j & 31)) * 2 + (j >> 5)] = Wfc[idx];
    }
    if (tid < 16) sb2[tid] = bV2[tid];
    if (tid < 64) sbf[tid] = bfc[tid];
    __syncthreads();

    int w = tid >> 5, lane = tid & 31;
    int grp   = lane >> 3;
    int myoff = lane & 7;
    int nwarp = (gridDim.x * blockDim.x) >> 5;

    for (int gw = (blockIdx.x * 256 + tid) >> 5; gw < NUM_U + NUM_I; gw += nwarp) {
        const uint2* f4; const float* pa; const int* rp; const int* col;
        const float* m2; const float* Eemb; float pbn; int nd; size_t orow_off;
        if (gw < NUM_I) {
            nd = gw;         f4 = reinterpret_cast<const uint2*>(g_h2u);
            pa = g_pa2_u; pbn = g_pb2_i[nd]; rp = g_rp_i; col = g_col_i;
            m2 = g_m2i; Eemb = Ei; orow_off = (size_t)(NUM_U + nd) * 128;
        } else {
            nd = gw - NUM_I; f4 = reinterpret_cast<const uint2*>(g_h2i);
            pa = g_pa2_i; pbn = g_pb2_u[nd]; rp = g_rp_u; col = g_col_u;
            m2 = g_m2u; Eemb = Eu; orow_off = (size_t)nd * 128;
        }
        int beg = rp[nd];
        int end = rp[nd + 1];
        float a0 = 0.f, a1 = 0.f, a2 = 0.f, a3 = 0.f, ssum = 0.f;

        for (int base = beg; base < end; base += 32) {
            int j = base + lane;
            float w_ = 0.f;
            int nbr = 0;
            if (j < end) {
                nbr = col[j];
                float x  = pa[nbr] + pbn;
                float sg = __fdividef(1.f, 1.f + __expf(-x));
                w_ = __expf(sg);
            }
            ssum += w_;
            int cnt = min(32, end - base);
            AGG_GATHER4(f4, a0, a1, a2, a3, w_, nbr, cnt, grp, myoff);
        }
        AGG_REDUCE4(a0, a1, a2, a3);
        #pragma unroll
        for (int o = 16; o; o >>= 1) ssum += __shfl_xor_sync(0xffffffffu, ssum, o);
        float inv = (end > beg) ? __fdividef(1.f, fmaxf(ssum, 1e-12f)) : 0.f;
        float sflag = (end > beg) ? 1.f : 0.f;

        if (lane < 8) {
            float4 o = make_float4(a0 * inv, a1 * inv, a2 * inv, a3 * inv);
            if (myoff < 4) {
                float4 zs = reinterpret_cast<const float4*>(m2)[nd * 8 + myoff];
                o.x += zs.x; o.y += zs.y; o.z += zs.z; o.w += zs.w;
            } else {
                int jb = 4 * (myoff - 4);
                o.x += sb2[jb] * sflag;     o.y += sb2[jb + 1] * sflag;
                o.z += sb2[jb + 2] * sflag; o.w += sb2[jb + 3] * sflag;
            }
            reinterpret_cast<float4*>(shv[w])[myoff] = o;
        }
        __syncwarp();

        float g0 = sbf[lane], g1 = sbf[lane + 32];
        #pragma unroll
        for (int k = 0; k < 32; k++) {
            float  c  = shv[w][k];
            float2 wv = sWf[k * 33 + lane];
            g0 = fmaf(c, wv.x, g0);
            g1 = fmaf(c, wv.y, g1);
        }
        g0 = fmaxf(g0, 0.f);
        g1 = fmaxf(g1, 0.f);

        float2 ev = reinterpret_cast<const float2*>(Eemb)[nd * 32 + lane];
        float* orow = outp + orow_off;
        reinterpret_cast<float2*>(orow)[lane] = ev;
        orow[64 + lane] = g0;
        orow[96 + lane] = g1;
        __syncwarp();
    }
}

// ---------------- host launcher ----------------
extern "C" void kernel_launch(void* const* d_in, const int* in_sizes, int n_in,
                              void* d_out, int out_size) {
    const float* E_u   = (const float*)d_in[0];
    const float* E_i   = (const float*)d_in[1];
    const float* Q_u   = (const float*)d_in[2];
    const float* Q_i   = (const float*)d_in[3];
    const float* Watt1 = (const float*)d_in[4];
    const float* Wupd1 = (const float*)d_in[5];
    const float* Watt2 = (const float*)d_in[8];
    const float* Wupd2 = (const float*)d_in[9];
    const float* WV2   = (const float*)d_in[10];
    const float* bV2   = (const float*)d_in[11];
    const float* Wfc   = (const float*)d_in[12];
    const float* bfc   = (const float*)d_in[13];
    const int*   src   = (const int*)d_in[14];
    const int*   dst   = (const int*)d_in[15];
    float* out = (float*)d_out;

    const int GB = 148 * 6;   // one residency wave at 6 blocks/SM

    k_hist_prep0<<<1184, 256>>>(src, dst, Q_u, Q_i, Watt1, Wupd1,
                                Wupd2, WV2, Watt2);                    // 0
    k_scan<<<2, 1024>>>();                                             // 1
    k_scatter_prep<<<GB, 256>>>(src, dst, Q_u, Q_i);                   // 2
    k_agg1<<<GB, 256>>>();                                             // 3 ← profiled
    k_agg_final<<<GB, 256>>>(E_u, E_i, bV2, Wfc, bfc, out);            // 4
}

// round 16
// speedup vs baseline: 1.0619x; 1.0111x over previous
#include <cuda_runtime.h>
#include <cuda_fp16.h>

#define NUM_U 50000
#define NUM_I 50000
#define NE    1000000

// ---------------- device scratch (static, allocation-free) ----------------
__device__ float   g_Ct[64 * 32];       // Ct[k][j] = C[j][k] (composed weights)
__device__ float   g_m1u[NUM_U * 32];   // t32 = q @ C.T (fp32 self term)
__device__ float   g_m1i[NUM_I * 32];
__device__ __half2 g_h1u[NUM_U * 16];   // fp16 mirror of t32 (gather, 64B rows)
__device__ __half2 g_h1i[NUM_I * 16];
__device__ float4  g_t3u[NUM_U];        // (pa1, ta, tb, pb1) per node
__device__ float4  g_t3i[NUM_I];
__device__ float   g_m2u[NUM_U * 32];   // [z2|v2] self (fp32)
__device__ float   g_m2i[NUM_I * 32];
__device__ __half2 g_h2u[NUM_U * 16];   // fp16 mirror of m2 (gather, 64B rows)
__device__ __half2 g_h2i[NUM_I * 16];
__device__ float   g_pa2_u[NUM_U], g_pb2_u[NUM_U];
__device__ float   g_pa2_i[NUM_I], g_pb2_i[NUM_I];
__device__ int4    g_e_i[NE];           // per-edge (col, w_bits, half2(w*ta,w*tb), 0)
__device__ int4    g_e_u[NE];
__device__ int     g_cnt_i[NUM_I], g_cnt_u[NUM_U];   // zero-init; re-zeroed by k_scan
__device__ int     g_cur_i[NUM_I], g_cur_u[NUM_U];
__device__ int     g_rp_i[NUM_I + 1], g_rp_u[NUM_U + 1];

__device__ __forceinline__ float edge_w(float x) {
    float sg = __fdividef(1.f, 1.f + __expf(-x));
    return __expf(sg);
}

// ---- launch 0: histogram + weight composition + light node projections --------
__global__ void __launch_bounds__(256) k_hist_prep0(
    const int* __restrict__ src, const int* __restrict__ dst,
    const float* __restrict__ Qu, const float* __restrict__ Qi,
    const float* __restrict__ watt1, const float* __restrict__ W1,
    const float* __restrict__ Wupd2, const float* __restrict__ WV2,
    const float* __restrict__ watt2) {
    __shared__ float sca[64], scb[64];
    int tid = threadIdx.x;
    if (tid < 128) {
        int which = tid >> 6, k = tid & 63;
        const float* R = watt2 + which * 64;
        float acc = 0.f;
        #pragma unroll 8
        for (int m = 0; m < 64; m++) acc = fmaf(R[m], W1[m * 64 + k], acc);
        (which ? scb : sca)[k] = acc;
    }
    if (blockIdx.x == 0) {
        for (int idx = tid; idx < 2048; idx += 256) {
            int j = idx >> 6, k = idx & 63;
            const float* R = (j < 16) ? (Wupd2 + j * 64) : (WV2 + (j - 16) * 64);
            float acc = 0.f;
            #pragma unroll 8
            for (int m = 0; m < 64; m++) acc = fmaf(R[m], W1[m * 64 + k], acc);
            g_Ct[k * 32 + j] = acc;
        }
    }
    __syncthreads();

    int nthread = gridDim.x * 256;
    for (int e = blockIdx.x * 256 + tid; e < NE; e += nthread) {
        atomicAdd(&g_cnt_i[dst[e]], 1);
        atomicAdd(&g_cnt_u[src[e]], 1);
    }

    int lane = tid & 31;
    int nwarp = nthread >> 5;
    float2 w1a = reinterpret_cast<const float2*>(watt1)[lane];
    float2 w1b = reinterpret_cast<const float2*>(watt1)[32 + lane];
    float2 cav = make_float2(sca[2 * lane], sca[2 * lane + 1]);
    float2 cbv = make_float2(scb[2 * lane], scb[2 * lane + 1]);

    for (int gw = (blockIdx.x * 256 + tid) >> 5; gw < NUM_U + NUM_I; gw += nwarp) {
        const float* q; float4* t3; int nd;
        if (gw < NUM_U) { nd = gw;         q = Qu; t3 = g_t3u; }
        else            { nd = gw - NUM_U; q = Qi; t3 = g_t3i; }
        float2 qv = reinterpret_cast<const float2*>(q)[nd * 32 + lane];
        float da = qv.x * w1a.x + qv.y * w1a.y;
        float db = qv.x * w1b.x + qv.y * w1b.y;
        float ta = qv.x * cav.x + qv.y * cav.y;
        float tb = qv.x * cbv.x + qv.y * cbv.y;
        #pragma unroll
        for (int o = 16; o; o >>= 1) {
            da += __shfl_xor_sync(0xffffffffu, da, o);
            db += __shfl_xor_sync(0xffffffffu, db, o);
            ta += __shfl_xor_sync(0xffffffffu, ta, o);
            tb += __shfl_xor_sync(0xffffffffu, tb, o);
        }
        if (lane == 0) t3[nd] = make_float4(da, ta, tb, db);
    }
}

// ---------------- launch 1: scan (re-zeros cnt for next replay) ----------------
__global__ void k_scan() {
    const int n = blockIdx.x ? NUM_U : NUM_I;
    int* cnt    = blockIdx.x ? g_cnt_u : g_cnt_i;
    int* cur    = blockIdx.x ? g_cur_u : g_cur_i;
    int* rp     = blockIdx.x ? g_rp_u  : g_rp_i;
    __shared__ int ssum[1024];
    int t = threadIdx.x;
    int C = (n + 1023) / 1024;
    int b = t * C;
    int e = min(n, b + C);
    int s = 0;
    #pragma unroll 4
    for (int i = b; i < e; i++) s += cnt[i];
    ssum[t] = s;
    __syncthreads();
    for (int off = 1; off < 1024; off <<= 1) {
        int v = (t >= off) ? ssum[t - off] : 0;
        __syncthreads();
        ssum[t] += v;
        __syncthreads();
    }
    int run = ssum[t] - s;
    for (int i = b; i < e; i++) {
        int c = cnt[i];
        rp[i]  = run;
        cur[i] = run;
        cnt[i] = 0;
        run += c;
    }
    if (t == 1023) rp[n] = ssum[1023];
}

// ---- launch 2: interleaved scatter (packed edge records) + m1 GEMV -------------
__global__ void __launch_bounds__(256, 6) k_scatter_prep(
    const int* __restrict__ src, const int* __restrict__ dst,
    const float* __restrict__ Qu, const float* __restrict__ Qi) {
    __shared__ float sCt[64 * 36];   // sCt[k*36 + j] = C[j][k]
    __shared__ float sx[8][64];
    int tid = threadIdx.x;
    for (int idx = tid; idx < 2048; idx += 256) {
        int j = idx & 31, k = idx >> 5;
        sCt[k * 36 + j] = g_Ct[idx];
    }
    __syncthreads();

    int w = tid >> 5, lane = tid & 31;
    int gwarp = blockIdx.x * 8 + w;
    const int NW = gridDim.x * 8;
    const int NCHUNK = NE / 32;              // 31250 exact

    const int ITERS = (NCHUNK + NW - 1) / NW;
    const int NITER = (NUM_U + NUM_I + 3 * NW - 1) / (3 * NW);
    const int TOT   = (ITERS > NITER) ? ITERS : NITER;

    for (int it = 0; it < TOT; ++it) {
        // ---- phase A: edge loads + atomics + edge-weight computation ----
        int c = gwarp + it * NW;
        int s = 0, d = 0, p = 0, q = 0;
        int4 rec_i = make_int4(0, 0, 0, 0), rec_u = make_int4(0, 0, 0, 0);
        bool has_e = (c < NCHUNK);
        if (has_e) {
            int e = c * 32 + lane;
            s = src[e];
            d = dst[e];
            float4 tu = g_t3u[s];
            float4 ti = g_t3i[d];
            p = atomicAdd(&g_cur_i[d], 1);
            q = atomicAdd(&g_cur_u[s], 1);
            float wi = edge_w(tu.x + ti.w);   // pa1_u[s] + pb1_i[d]
            float wu = edge_w(ti.x + tu.w);   // pa1_i[d] + pb1_u[s]
            __half2 hi = __floats2half2_rn(wi * tu.y, wi * tu.z);
            __half2 hu = __floats2half2_rn(wu * ti.y, wu * ti.z);
            rec_i = make_int4(s, __float_as_int(wi), *reinterpret_cast<int*>(&hi), 0);
            rec_u = make_int4(d, __float_as_int(wu), *reinterpret_cast<int*>(&hu), 0);
        }

        // ---- phase B: 3 nodes of m1 GEMV + h1 mirror (hides phase-A latency) ----
        #pragma unroll
        for (int r = 0; r < 3; ++r) {
            int gw = gwarp + (it * 3 + r) * NW;
            if (gw < NUM_U + NUM_I) {
                const float* qv_p; float* m1; __half2* h1; int nd;
                if (gw < NUM_U) { nd = gw;         qv_p = Qu; m1 = g_m1u; h1 = g_h1u; }
                else            { nd = gw - NUM_U; qv_p = Qi; m1 = g_m1i; h1 = g_h1i; }

                float2 qv = reinterpret_cast<const float2*>(qv_p)[nd * 32 + lane];
                sx[w][2 * lane]     = qv.x;
                sx[w][2 * lane + 1] = qv.y;
                __syncwarp();
                float acc = 0.f;
                #pragma unroll
                for (int k = 0; k < 64; k++) acc = fmaf(sx[w][k], sCt[k * 36 + lane], acc);
                m1[nd * 32 + lane] = acc;
                float other = __shfl_xor_sync(0xffffffffu, acc, 1);
                if (!(lane & 1)) h1[nd * 16 + (lane >> 1)] = __floats2half2_rn(acc, other);
                __syncwarp();
            }
        }

        // ---- phase C: consume atomic results (single 16B store per side) ----
        if (has_e) {
            g_e_i[p] = rec_i;
            g_e_u[q] = rec_u;
        }
    }
}

// 4-neighbor gather: lane groups of 8; each lane 8B of a 64B fp16 row
#define AGG_GATHER4(f4, a0, a1, a2, a3, w_, nbr, cnt, grp, myoff)                      \
    _Pragma("unroll 4")                                                                \
    for (int t = 0; t < cnt; t += 4) {                                                 \
        int srcl = t + (grp);                                                          \
        float wt = __shfl_sync(0xffffffffu, w_, srcl);                                 \
        int   nb = __shfl_sync(0xffffffffu, nbr, srcl);                                \
        uint2 pv = (f4)[nb * 8 + (myoff)];                                             \
        float2 v0 = __half22float2(*reinterpret_cast<__half2*>(&pv.x));                \
        float2 v1 = __half22float2(*reinterpret_cast<__half2*>(&pv.y));                \
        a0 = fmaf(wt, v0.x, a0);                                                       \
        a1 = fmaf(wt, v0.y, a1);                                                       \
        a2 = fmaf(wt, v1.x, a2);                                                       \
        a3 = fmaf(wt, v1.y, a3);                                                       \
    }

#define AGG_REDUCE4(a0, a1, a2, a3)                                                    \
    a0 += __shfl_xor_sync(0xffffffffu, a0, 8);                                         \
    a1 += __shfl_xor_sync(0xffffffffu, a1, 8);                                         \
    a2 += __shfl_xor_sync(0xffffffffu, a2, 8);                                         \
    a3 += __shfl_xor_sync(0xffffffffu, a3, 8);                                         \
    a0 += __shfl_xor_sync(0xffffffffu, a0, 16);                                        \
    a1 += __shfl_xor_sync(0xffffffffu, a1, 16);                                        \
    a2 += __shfl_xor_sync(0xffffffffu, a2, 16);                                        \
    a3 += __shfl_xor_sync(0xffffffffu, a3, 16);

// ---- launch 3: layer-1 agg (packed edge records) + layer-2 self terms ----------
__global__ void __launch_bounds__(256, 6) k_agg1() {
    int tid  = threadIdx.x;
    int lane = tid & 31;
    int grp   = lane >> 3;
    int myoff = lane & 7;
    int nwarp = (gridDim.x * blockDim.x) >> 5;

    for (int gw = (blockIdx.x * 256 + tid) >> 5; gw < NUM_U + NUM_I; gw += nwarp) {
        const uint2* f4; const int* rp; const int4* ev;
        const float* m1s; const float4* t3s;
        float* m2; __half2* h2; float* pa2; float* pb2; int nd;
        if (gw < NUM_I) {
            nd = gw;         f4 = reinterpret_cast<const uint2*>(g_h1u);
            rp = g_rp_i; ev = g_e_i;
            m1s = g_m1i; t3s = g_t3i;
            m2 = g_m2i; h2 = g_h2i; pa2 = g_pa2_i; pb2 = g_pb2_i;
        } else {
            nd = gw - NUM_I; f4 = reinterpret_cast<const uint2*>(g_h1i);
            rp = g_rp_u; ev = g_e_u;
            m1s = g_m1u; t3s = g_t3u;
            m2 = g_m2u; h2 = g_h2u; pa2 = g_pa2_u; pb2 = g_pb2_u;
        }
        int beg = rp[nd];
        int end = rp[nd + 1];
        float a0 = 0.f, a1 = 0.f, a2 = 0.f, a3 = 0.f;
        float ssum = 0.f, sa = 0.f, sb = 0.f;

        for (int base = beg; base < end; base += 32) {
            int j = base + lane;
            float w_ = 0.f;
            int nbr = 0;
            if (j < end) {
                int4 rec = ev[j];
                nbr = rec.x;
                w_  = __int_as_float(rec.y);
                float2 t = __half22float2(*reinterpret_cast<__half2*>(&rec.z));
                sa += t.x;
                sb += t.y;
            }
            ssum += w_;
            int cnt = min(32, end - base);
            AGG_GATHER4(f4, a0, a1, a2, a3, w_, nbr, cnt, grp, myoff);
        }
        AGG_REDUCE4(a0, a1, a2, a3);
        #pragma unroll
        for (int o = 16; o; o >>= 1) {
            ssum += __shfl_xor_sync(0xffffffffu, ssum, o);
            sa   += __shfl_xor_sync(0xffffffffu, sa, o);
            sb   += __shfl_xor_sync(0xffffffffu, sb, o);
        }
        float inv = (end > beg) ? __fdividef(1.f, fmaxf(ssum, 1e-12f)) : 0.f;

        if (lane == 0) {
            float4 ts = t3s[nd];
            pa2[nd] = fmaf(sa, inv, ts.y);
            pb2[nd] = fmaf(sb, inv, ts.z);
        }
        if (lane < 8) {
            float4 ms = reinterpret_cast<const float4*>(m1s)[nd * 8 + myoff];
            float4 o = make_float4(fmaf(a0, inv, ms.x), fmaf(a1, inv, ms.y),
                                   fmaf(a2, inv, ms.z), fmaf(a3, inv, ms.w));
            reinterpret_cast<float4*>(m2)[nd * 8 + myoff] = o;
            h2[nd * 16 + 2 * myoff]     = __floats2half2_rn(o.x, o.y);
            h2[nd * 16 + 2 * myoff + 1] = __floats2half2_rn(o.z, o.w);
        }
        __syncwarp();
    }
}

// ---------------- launch 4: layer-2 agg (on m2) + fc + output concat ------------
__global__ void __launch_bounds__(256, 6) k_agg_final(
    const float* __restrict__ Eu, const float* __restrict__ Ei,
    const float* __restrict__ bV2, const float* __restrict__ Wfc,
    const float* __restrict__ bfc, float* __restrict__ outp) {

    __shared__ float2 sWf[32 * 33];  // sWf[k*33+l] = (Wfc[l][k], Wfc[l+32][k])
    __shared__ float  shv[8][32];
    __shared__ float  sb2[16], sbf[64];
    int tid = threadIdx.x;
    for (int idx = tid; idx < 2048; idx += 256) {
        int j = idx >> 5, k = idx & 31;
        reinterpret_cast<float*>(sWf)[(k * 33 + (j & 31)) * 2 + (j >> 5)] = Wfc[idx];
    }
    if (tid < 16) sb2[tid] = bV2[tid];
    if (tid < 64) sbf[tid] = bfc[tid];
    __syncthreads();

    int w = tid >> 5, lane = tid & 31;
    int grp   = lane >> 3;
    int myoff = lane & 7;
    int nwarp = (gridDim.x * blockDim.x) >> 5;

    for (int gw = (blockIdx.x * 256 + tid) >> 5; gw < NUM_U + NUM_I; gw += nwarp) {
        const uint2* f4; const float* pa; const int* rp; const int4* ev;
        const float* m2; const float* Eemb; float pbn; int nd; size_t orow_off;
        if (gw < NUM_I) {
            nd = gw;         f4 = reinterpret_cast<const uint2*>(g_h2u);
            pa = g_pa2_u; pbn = g_pb2_i[nd]; rp = g_rp_i; ev = g_e_i;
            m2 = g_m2i; Eemb = Ei; orow_off = (size_t)(NUM_U + nd) * 128;
        } else {
            nd = gw - NUM_I; f4 = reinterpret_cast<const uint2*>(g_h2i);
            pa = g_pa2_i; pbn = g_pb2_u[nd]; rp = g_rp_u; ev = g_e_u;
            m2 = g_m2u; Eemb = Eu; orow_off = (size_t)nd * 128;
        }
        int beg = rp[nd];
        int end = rp[nd + 1];
        float a0 = 0.f, a1 = 0.f, a2 = 0.f, a3 = 0.f, ssum = 0.f;

        for (int base = beg; base < end; base += 32) {
            int j = base + lane;
            float w_ = 0.f;
            int nbr = 0;
            if (j < end) {
                nbr = ev[j].x;
                float x  = pa[nbr] + pbn;
                float sg = __fdividef(1.f, 1.f + __expf(-x));
                w_ = __expf(sg);
            }
            ssum += w_;
            int cnt = min(32, end - base);
            AGG_GATHER4(f4, a0, a1, a2, a3, w_, nbr, cnt, grp, myoff);
        }
        AGG_REDUCE4(a0, a1, a2, a3);
        #pragma unroll
        for (int o = 16; o; o >>= 1) ssum += __shfl_xor_sync(0xffffffffu, ssum, o);
        float inv = (end > beg) ? __fdividef(1.f, fmaxf(ssum, 1e-12f)) : 0.f;
        float sflag = (end > beg) ? 1.f : 0.f;

        if (lane < 8) {
            float4 o = make_float4(a0 * inv, a1 * inv, a2 * inv, a3 * inv);
            if (myoff < 4) {
                float4 zs = reinterpret_cast<const float4*>(m2)[nd * 8 + myoff];
                o.x += zs.x; o.y += zs.y; o.z += zs.z; o.w += zs.w;
            } else {
                int jb = 4 * (myoff - 4);
                o.x += sb2[jb] * sflag;     o.y += sb2[jb + 1] * sflag;
                o.z += sb2[jb + 2] * sflag; o.w += sb2[jb + 3] * sflag;
            }
            reinterpret_cast<float4*>(shv[w])[myoff] = o;
        }
        __syncwarp();

        float g0 = sbf[lane], g1 = sbf[lane + 32];
        #pragma unroll
        for (int k = 0; k < 32; k++) {
            float  c  = shv[w][k];
            float2 wv = sWf[k * 33 + lane];
            g0 = fmaf(c, wv.x, g0);
            g1 = fmaf(c, wv.y, g1);
        }
        g0 = fmaxf(g0, 0.f);
        g1 = fmaxf(g1, 0.f);

        float2 ev2 = reinterpret_cast<const float2*>(Eemb)[nd * 32 + lane];
        float* orow = outp + orow_off;
        reinterpret_cast<float2*>(orow)[lane] = ev2;
        orow[64 + lane] = g0;
        orow[96 + lane] = g1;
        __syncwarp();
    }
}

// ---------------- host launcher ----------------
extern "C" void kernel_launch(void* const* d_in, const int* in_sizes, int n_in,
                              void* d_out, int out_size) {
    const float* E_u   = (const float*)d_in[0];
    const float* E_i   = (const float*)d_in[1];
    const float* Q_u   = (const float*)d_in[2];
    const float* Q_i   = (const float*)d_in[3];
    const float* Watt1 = (const float*)d_in[4];
    const float* Wupd1 = (const float*)d_in[5];
    const float* Watt2 = (const float*)d_in[8];
    const float* Wupd2 = (const float*)d_in[9];
    const float* WV2   = (const float*)d_in[10];
    const float* bV2   = (const float*)d_in[11];
    const float* Wfc   = (const float*)d_in[12];
    const float* bfc   = (const float*)d_in[13];
    const int*   src   = (const int*)d_in[14];
    const int*   dst   = (const int*)d_in[15];
    float* out = (float*)d_out;

    const int GB = 148 * 6;   // one residency wave at 6 blocks/SM

    k_hist_prep0<<<1184, 256>>>(src, dst, Q_u, Q_i, Watt1, Wupd1,
                                Wupd2, WV2, Watt2);                    // 0
    k_scan<<<2, 1024>>>();                                             // 1
    k_scatter_prep<<<GB, 256>>>(src, dst, Q_u, Q_i);                   // 2
    k_agg1<<<GB, 256>>>();                                             // 3 ← profiled
    k_agg_final<<<GB, 256>>>(E_u, E_i, bV2, Wfc, bfc, out);            // 4
}

// round 17
// speedup vs baseline: 1.0621x; 1.0002x over previous
#include <cuda_runtime.h>
#include <cuda_fp16.h>

#define NUM_U 50000
#define NUM_I 50000
#define NE    1000000

// ---------------- device scratch (static, allocation-free) ----------------
__device__ float   g_Ct[64 * 32];       // Ct[k][j] = C[j][k] (composed weights)
__device__ float   g_m1u[NUM_U * 32];   // t32 = q @ C.T (fp32 self term)
__device__ float   g_m1i[NUM_I * 32];
__device__ __half2 g_h1u[NUM_U * 16];   // fp16 mirror of t32 (gather, 64B rows)
__device__ __half2 g_h1i[NUM_I * 16];
__device__ float4  g_t3u[NUM_U];        // (pa1, ta, tb, pb1) per node
__device__ float4  g_t3i[NUM_I];
__device__ float   g_m2u[NUM_U * 32];   // [z2|v2] self (fp32)
__device__ float   g_m2i[NUM_I * 32];
__device__ __half2 g_h2u[NUM_U * 16];   // fp16 mirror of m2 (gather, 64B rows)
__device__ __half2 g_h2i[NUM_I * 16];
__device__ float   g_pa2_u[NUM_U], g_pb2_u[NUM_U];
__device__ float   g_pa2_i[NUM_I], g_pb2_i[NUM_I];
__device__ int4    g_e_i[NE];           // per-edge (col, w1_bits, half2(w*ta,w*tb), xpos)
__device__ int4    g_e_u[NE];
__device__ float   g_w2_i[NE];          // per-edge forwarded pa2 of neighbor (layer 2)
__device__ float   g_w2_u[NE];
__device__ int     g_cnt_i[NUM_I], g_cnt_u[NUM_U];   // zero-init; re-zeroed by k_scan
__device__ int     g_cur_i[NUM_I], g_cur_u[NUM_U];
__device__ int     g_rp_i[NUM_I + 1], g_rp_u[NUM_U + 1];

__device__ __forceinline__ float edge_w(float x) {
    float sg = __fdividef(1.f, 1.f + __expf(-x));
    return __expf(sg);
}

// ---- launch 0: histogram + weight composition + light node projections --------
__global__ void __launch_bounds__(256) k_hist_prep0(
    const int* __restrict__ src, const int* __restrict__ dst,
    const float* __restrict__ Qu, const float* __restrict__ Qi,
    const float* __restrict__ watt1, const float* __restrict__ W1,
    const float* __restrict__ Wupd2, const float* __restrict__ WV2,
    const float* __restrict__ watt2) {
    __shared__ float sca[64], scb[64];
    int tid = threadIdx.x;
    if (tid < 128) {
        int which = tid >> 6, k = tid & 63;
        const float* R = watt2 + which * 64;
        float acc = 0.f;
        #pragma unroll 8
        for (int m = 0; m < 64; m++) acc = fmaf(R[m], W1[m * 64 + k], acc);
        (which ? scb : sca)[k] = acc;
    }
    if (blockIdx.x == 0) {
        for (int idx = tid; idx < 2048; idx += 256) {
            int j = idx >> 6, k = idx & 63;
            const float* R = (j < 16) ? (Wupd2 + j * 64) : (WV2 + (j - 16) * 64);
            float acc = 0.f;
            #pragma unroll 8
            for (int m = 0; m < 64; m++) acc = fmaf(R[m], W1[m * 64 + k], acc);
            g_Ct[k * 32 + j] = acc;
        }
    }
    __syncthreads();

    int nthread = gridDim.x * 256;
    for (int e = blockIdx.x * 256 + tid; e < NE; e += nthread) {
        atomicAdd(&g_cnt_i[dst[e]], 1);
        atomicAdd(&g_cnt_u[src[e]], 1);
    }

    int lane = tid & 31;
    int nwarp = nthread >> 5;
    float2 w1a = reinterpret_cast<const float2*>(watt1)[lane];
    float2 w1b = reinterpret_cast<const float2*>(watt1)[32 + lane];
    float2 cav = make_float2(sca[2 * lane], sca[2 * lane + 1]);
    float2 cbv = make_float2(scb[2 * lane], scb[2 * lane + 1]);

    for (int gw = (blockIdx.x * 256 + tid) >> 5; gw < NUM_U + NUM_I; gw += nwarp) {
        const float* q; float4* t3; int nd;
        if (gw < NUM_U) { nd = gw;         q = Qu; t3 = g_t3u; }
        else            { nd = gw - NUM_U; q = Qi; t3 = g_t3i; }
        float2 qv = reinterpret_cast<const float2*>(q)[nd * 32 + lane];
        float da = qv.x * w1a.x + qv.y * w1a.y;
        float db = qv.x * w1b.x + qv.y * w1b.y;
        float ta = qv.x * cav.x + qv.y * cav.y;
        float tb = qv.x * cbv.x + qv.y * cbv.y;
        #pragma unroll
        for (int o = 16; o; o >>= 1) {
            da += __shfl_xor_sync(0xffffffffu, da, o);
            db += __shfl_xor_sync(0xffffffffu, db, o);
            ta += __shfl_xor_sync(0xffffffffu, ta, o);
            tb += __shfl_xor_sync(0xffffffffu, tb, o);
        }
        if (lane == 0) t3[nd] = make_float4(da, ta, tb, db);
    }
}

// ---------------- launch 1: scan (re-zeros cnt for next replay) ----------------
__global__ void k_scan() {
    const int n = blockIdx.x ? NUM_U : NUM_I;
    int* cnt    = blockIdx.x ? g_cnt_u : g_cnt_i;
    int* cur    = blockIdx.x ? g_cur_u : g_cur_i;
    int* rp     = blockIdx.x ? g_rp_u  : g_rp_i;
    __shared__ int ssum[1024];
    int t = threadIdx.x;
    int C = (n + 1023) / 1024;
    int b = t * C;
    int e = min(n, b + C);
    int s = 0;
    #pragma unroll 4
    for (int i = b; i < e; i++) s += cnt[i];
    ssum[t] = s;
    __syncthreads();
    for (int off = 1; off < 1024; off <<= 1) {
        int v = (t >= off) ? ssum[t - off] : 0;
        __syncthreads();
        ssum[t] += v;
        __syncthreads();
    }
    int run = ssum[t] - s;
    for (int i = b; i < e; i++) {
        int c = cnt[i];
        rp[i]  = run;
        cur[i] = run;
        cnt[i] = 0;
        run += c;
    }
    if (t == 1023) rp[n] = ssum[1023];
}

// ---- launch 2: interleaved scatter (packed edge records) + m1 GEMV -------------
__global__ void __launch_bounds__(256, 6) k_scatter_prep(
    const int* __restrict__ src, const int* __restrict__ dst,
    const float* __restrict__ Qu, const float* __restrict__ Qi) {
    __shared__ float sCt[64 * 36];   // sCt[k*36 + j] = C[j][k]
    __shared__ float sx[8][64];
    int tid = threadIdx.x;
    for (int idx = tid; idx < 2048; idx += 256) {
        int j = idx & 31, k = idx >> 5;
        sCt[k * 36 + j] = g_Ct[idx];
    }
    __syncthreads();

    int w = tid >> 5, lane = tid & 31;
    int gwarp = blockIdx.x * 8 + w;
    const int NW = gridDim.x * 8;
    const int NCHUNK = NE / 32;              // 31250 exact

    const int ITERS = (NCHUNK + NW - 1) / NW;
    const int NITER = (NUM_U + NUM_I + 3 * NW - 1) / (3 * NW);
    const int TOT   = (ITERS > NITER) ? ITERS : NITER;

    for (int it = 0; it < TOT; ++it) {
        // ---- phase A: edge loads + atomics + edge-weight computation ----
        int c = gwarp + it * NW;
        int s = 0, d = 0, p = 0, q = 0;
        float wi = 0.f, wu = 0.f;
        int hibits = 0, hubits = 0;
        bool has_e = (c < NCHUNK);
        if (has_e) {
            int e = c * 32 + lane;
            s = src[e];
            d = dst[e];
            float4 tu = g_t3u[s];
            float4 ti = g_t3i[d];
            p = atomicAdd(&g_cur_i[d], 1);
            q = atomicAdd(&g_cur_u[s], 1);
            wi = edge_w(tu.x + ti.w);   // pa1_u[s] + pb1_i[d]
            wu = edge_w(ti.x + tu.w);   // pa1_i[d] + pb1_u[s]
            __half2 hi = __floats2half2_rn(wi * tu.y, wi * tu.z);
            __half2 hu = __floats2half2_rn(wu * ti.y, wu * ti.z);
            hibits = *reinterpret_cast<int*>(&hi);
            hubits = *reinterpret_cast<int*>(&hu);
        }

        // ---- phase B: 3 nodes of m1 GEMV + h1 mirror (hides phase-A latency) ----
        #pragma unroll
        for (int r = 0; r < 3; ++r) {
            int gw = gwarp + (it * 3 + r) * NW;
            if (gw < NUM_U + NUM_I) {
                const float* qv_p; float* m1; __half2* h1; int nd;
                if (gw < NUM_U) { nd = gw;         qv_p = Qu; m1 = g_m1u; h1 = g_h1u; }
                else            { nd = gw - NUM_U; qv_p = Qi; m1 = g_m1i; h1 = g_h1i; }

                float2 qv = reinterpret_cast<const float2*>(qv_p)[nd * 32 + lane];
                sx[w][2 * lane]     = qv.x;
                sx[w][2 * lane + 1] = qv.y;
                __syncwarp();
                float acc = 0.f;
                #pragma unroll
                for (int k = 0; k < 64; k++) acc = fmaf(sx[w][k], sCt[k * 36 + lane], acc);
                m1[nd * 32 + lane] = acc;
                float other = __shfl_xor_sync(0xffffffffu, acc, 1);
                if (!(lane & 1)) h1[nd * 16 + (lane >> 1)] = __floats2half2_rn(acc, other);
                __syncwarp();
            }
        }

        // ---- phase C: consume atomic results (single 16B store per side) ----
        // .w holds the cross-side CSR position (for layer-2 pa2 forwarding)
        if (has_e) {
            g_e_i[p] = make_int4(s, __float_as_int(wi), hibits, q);
            g_e_u[q] = make_int4(d, __float_as_int(wu), hubits, p);
        }
    }
}

// 4-neighbor gather: lane groups of 8; each lane 8B of a 64B fp16 row
#define AGG_GATHER4(f4, a0, a1, a2, a3, w_, nbr, cnt, grp, myoff)                      \
    _Pragma("unroll 4")                                                                \
    for (int t = 0; t < cnt; t += 4) {                                                 \
        int srcl = t + (grp);                                                          \
        float wt = __shfl_sync(0xffffffffu, w_, srcl);                                 \
        int   nb = __shfl_sync(0xffffffffu, nbr, srcl);                                \
        uint2 pv = (f4)[nb * 8 + (myoff)];                                             \
        float2 v0 = __half22float2(*reinterpret_cast<__half2*>(&pv.x));                \
        float2 v1 = __half22float2(*reinterpret_cast<__half2*>(&pv.y));                \
        a0 = fmaf(wt, v0.x, a0);                                                       \
        a1 = fmaf(wt, v0.y, a1);                                                       \
        a2 = fmaf(wt, v1.x, a2);                                                       \
        a3 = fmaf(wt, v1.y, a3);                                                       \
    }

#define AGG_REDUCE4(a0, a1, a2, a3)                                                    \
    a0 += __shfl_xor_sync(0xffffffffu, a0, 8);                                         \
    a1 += __shfl_xor_sync(0xffffffffu, a1, 8);                                         \
    a2 += __shfl_xor_sync(0xffffffffu, a2, 8);                                         \
    a3 += __shfl_xor_sync(0xffffffffu, a3, 8);                                         \
    a0 += __shfl_xor_sync(0xffffffffu, a0, 16);                                        \
    a1 += __shfl_xor_sync(0xffffffffu, a1, 16);                                        \
    a2 += __shfl_xor_sync(0xffffffffu, a2, 16);                                        \
    a3 += __shfl_xor_sync(0xffffffffu, a3, 16);

// ---- launch 3: layer-1 agg + layer-2 self terms + pa2 edge-forwarding ----------
__global__ void __launch_bounds__(256, 6) k_agg1() {
    int tid  = threadIdx.x;
    int lane = tid & 31;
    int grp   = lane >> 3;
    int myoff = lane & 7;
    int nwarp = (gridDim.x * blockDim.x) >> 5;

    for (int gw = (blockIdx.x * 256 + tid) >> 5; gw < NUM_U + NUM_I; gw += nwarp) {
        const uint2* f4; const int* rp; const int4* ev;
        const float* m1s; const float4* t3s;
        float* m2; __half2* h2; float* pa2; float* pb2; float* w2x; int nd;
        if (gw < NUM_I) {
            nd = gw;         f4 = reinterpret_cast<const uint2*>(g_h1u);
            rp = g_rp_i; ev = g_e_i;
            m1s = g_m1i; t3s = g_t3i;
            m2 = g_m2i; h2 = g_h2i; pa2 = g_pa2_i; pb2 = g_pb2_i;
            w2x = g_w2_u;   // forward pa2_i to user-side edge slots
        } else {
            nd = gw - NUM_I; f4 = reinterpret_cast<const uint2*>(g_h1i);
            rp = g_rp_u; ev = g_e_u;
            m1s = g_m1u; t3s = g_t3u;
            m2 = g_m2u; h2 = g_h2u; pa2 = g_pa2_u; pb2 = g_pb2_u;
            w2x = g_w2_i;   // forward pa2_u to item-side edge slots
        }
        int beg = rp[nd];
        int end = rp[nd + 1];
        float a0 = 0.f, a1 = 0.f, a2 = 0.f, a3 = 0.f;
        float ssum = 0.f, sa = 0.f, sb = 0.f;

        for (int base = beg; base < end; base += 32) {
            int j = base + lane;
            float w_ = 0.f;
            int nbr = 0;
            if (j < end) {
                int4 rec = ev[j];
                nbr = rec.x;
                w_  = __int_as_float(rec.y);
                float2 t = __half22float2(*reinterpret_cast<__half2*>(&rec.z));
                sa += t.x;
                sb += t.y;
            }
            ssum += w_;
            int cnt = min(32, end - base);
            AGG_GATHER4(f4, a0, a1, a2, a3, w_, nbr, cnt, grp, myoff);
        }
        AGG_REDUCE4(a0, a1, a2, a3);
        #pragma unroll
        for (int o = 16; o; o >>= 1) {
            ssum += __shfl_xor_sync(0xffffffffu, ssum, o);
            sa   += __shfl_xor_sync(0xffffffffu, sa, o);
            sb   += __shfl_xor_sync(0xffffffffu, sb, o);
        }
        float inv = (end > beg) ? __fdividef(1.f, fmaxf(ssum, 1e-12f)) : 0.f;

        // all lanes compute pa2 (t3s[nd] is a broadcast load)
        float4 ts = t3s[nd];
        float pa2v = fmaf(sa, inv, ts.y);
        if (lane == 0) {
            pa2[nd] = pa2v;
            pb2[nd] = fmaf(sb, inv, ts.z);
        }
        // forward pa2 to the opposite side's per-edge slots (coalesced read, scattered ST)
        for (int j = beg + lane; j < end; j += 32) {
            w2x[ev[j].w] = pa2v;
        }
        if (lane < 8) {
            float4 ms = reinterpret_cast<const float4*>(m1s)[nd * 8 + myoff];
            float4 o = make_float4(fmaf(a0, inv, ms.x), fmaf(a1, inv, ms.y),
                                   fmaf(a2, inv, ms.z), fmaf(a3, inv, ms.w));
            reinterpret_cast<float4*>(m2)[nd * 8 + myoff] = o;
            h2[nd * 16 + 2 * myoff]     = __floats2half2_rn(o.x, o.y);
            h2[nd * 16 + 2 * myoff + 1] = __floats2half2_rn(o.z, o.w);
        }
        __syncwarp();
    }
}

// ---------------- launch 4: layer-2 agg (coalesced w2) + fc + output concat -----
__global__ void __launch_bounds__(256, 6) k_agg_final(
    const float* __restrict__ Eu, const float* __restrict__ Ei,
    const float* __restrict__ bV2, const float* __restrict__ Wfc,
    const float* __restrict__ bfc, float* __restrict__ outp) {

    __shared__ float2 sWf[32 * 33];  // sWf[k*33+l] = (Wfc[l][k], Wfc[l+32][k])
    __shared__ float  shv[8][32];
    __shared__ float  sb2[16], sbf[64];
    int tid = threadIdx.x;
    for (int idx = tid; idx < 2048; idx += 256) {
        int j = idx >> 5, k = idx & 31;
        reinterpret_cast<float*>(sWf)[(k * 33 + (j & 31)) * 2 + (j >> 5)] = Wfc[idx];
    }
    if (tid < 16) sb2[tid] = bV2[tid];
    if (tid < 64) sbf[tid] = bfc[tid];
    __syncthreads();

    int w = tid >> 5, lane = tid & 31;
    int grp   = lane >> 3;
    int myoff = lane & 7;
    int nwarp = (gridDim.x * blockDim.x) >> 5;

    for (int gw = (blockIdx.x * 256 + tid) >> 5; gw < NUM_U + NUM_I; gw += nwarp) {
        const uint2* f4; const int* rp; const int4* ev; const float* w2;
        const float* m2; const float* Eemb; float pbn; int nd; size_t orow_off;
        if (gw < NUM_I) {
            nd = gw;         f4 = reinterpret_cast<const uint2*>(g_h2u);
            pbn = g_pb2_i[nd]; rp = g_rp_i; ev = g_e_i; w2 = g_w2_i;
            m2 = g_m2i; Eemb = Ei; orow_off = (size_t)(NUM_U + nd) * 128;
        } else {
            nd = gw - NUM_I; f4 = reinterpret_cast<const uint2*>(g_h2i);
            pbn = g_pb2_u[nd]; rp = g_rp_u; ev = g_e_u; w2 = g_w2_u;
            m2 = g_m2u; Eemb = Eu; orow_off = (size_t)nd * 128;
        }
        int beg = rp[nd];
        int end = rp[nd + 1];
        float a0 = 0.f, a1 = 0.f, a2 = 0.f, a3 = 0.f, ssum = 0.f;

        for (int base = beg; base < end; base += 32) {
            int j = base + lane;
            float w_ = 0.f;
            int nbr = 0;
            if (j < end) {
                nbr = ev[j].x;
                w_  = edge_w(w2[j] + pbn);
            }
            ssum += w_;
            int cnt = min(32, end - base);
            AGG_GATHER4(f4, a0, a1, a2, a3, w_, nbr, cnt, grp, myoff);
        }
        AGG_REDUCE4(a0, a1, a2, a3);
        #pragma unroll
        for (int o = 16; o; o >>= 1) ssum += __shfl_xor_sync(0xffffffffu, ssum, o);
        float inv = (end > beg) ? __fdividef(1.f, fmaxf(ssum, 1e-12f)) : 0.f;
        float sflag = (end > beg) ? 1.f : 0.f;

        if (lane < 8) {
            float4 o = make_float4(a0 * inv, a1 * inv, a2 * inv, a3 * inv);
            if (myoff < 4) {
                float4 zs = reinterpret_cast<const float4*>(m2)[nd * 8 + myoff];
                o.x += zs.x; o.y += zs.y; o.z += zs.z; o.w += zs.w;
            } else {
                int jb = 4 * (myoff - 4);
                o.x += sb2[jb] * sflag;     o.y += sb2[jb + 1] * sflag;
                o.z += sb2[jb + 2] * sflag; o.w += sb2[jb + 3] * sflag;
            }
            reinterpret_cast<float4*>(shv[w])[myoff] = o;
        }
        __syncwarp();

        float g0 = sbf[lane], g1 = sbf[lane + 32];
        #pragma unroll
        for (int k = 0; k < 32; k++) {
            float  c  = shv[w][k];
            float2 wv = sWf[k * 33 + lane];
            g0 = fmaf(c, wv.x, g0);
            g1 = fmaf(c, wv.y, g1);
        }
        g0 = fmaxf(g0, 0.f);
        g1 = fmaxf(g1, 0.f);

        float2 ev2 = reinterpret_cast<const float2*>(Eemb)[nd * 32 + lane];
        float* orow = outp + orow_off;
        reinterpret_cast<float2*>(orow)[lane] = ev2;
        orow[64 + lane] = g0;
        orow[96 + lane] = g1;
        __syncwarp();
    }
}

// ---------------- host launcher ----------------
extern "C" void kernel_launch(void* const* d_in, const int* in_sizes, int n_in,
                              void* d_out, int out_size) {
    const float* E_u   = (const float*)d_in[0];
    const float* E_i   = (const float*)d_in[1];
    const float* Q_u   = (const float*)d_in[2];
    const float* Q_i   = (const float*)d_in[3];
    const float* Watt1 = (const float*)d_in[4];
    const float* Wupd1 = (const float*)d_in[5];
    const float* Watt2 = (const float*)d_in[8];
    const float* Wupd2 = (const float*)d_in[9];
    const float* WV2   = (const float*)d_in[10];
    const float* bV2   = (const float*)d_in[11];
    const float* Wfc   = (const float*)d_in[12];
    const float* bfc   = (const float*)d_in[13];
    const int*   src   = (const int*)d_in[14];
    const int*   dst   = (const int*)d_in[15];
    float* out = (float*)d_out;

    const int GB = 148 * 6;   // one residency wave at 6 blocks/SM

    k_hist_prep0<<<1184, 256>>>(src, dst, Q_u, Q_i, Watt1, Wupd1,
                                Wupd2, WV2, Watt2);                    // 0
    k_scan<<<2, 1024>>>();                                             // 1
    k_scatter_prep<<<GB, 256>>>(src, dst, Q_u, Q_i);                   // 2
    k_agg1<<<GB, 256>>>();                                             // 3 ← profiled
    k_agg_final<<<GB, 256>>>(E_u, E_i, bV2, Wfc, bfc, out);            // 4
}